// round 14
// baseline (speedup 1.0000x reference)
#include <cuda_runtime.h>
#include <cstdint>

#define NG    1024
#define DIM   128
#define HID   512
#define NREP  32
#define EB    1184     // edge blocks in fused kernel

// ---- scratch (no allocations allowed) ----
// Zero-initialized at load; mlp2_kernel re-zeroes after the pipeline consumed
// it, so every kernel_launch call observes zeroed scratch (graph-replay safe).
__device__ float    d_escratch[NREP * NG * DIM];   // 16 MB replicated edge sums
__device__ unsigned d_ecnt[NREP * NG];             // replicated edge counts
__device__ float    d_node_mean[NG * DIM];
__device__ float    d_hbuf[NG * HID];              // hidden activations (2 MB)

// ---------------------------------------------------------------------------
__device__ __forceinline__ int load_idx(const void* p, long long i, int idx64) {
    return idx64 ? (int)((const long long*)p)[i] : ((const int*)p)[i];
}
// dtype probe on edge_index: node ids are random nonzero ints, so
// all-zero odd 32-bit words <=> int64 storage.
__device__ __forceinline__ int probe_idx64(const void* edge_index) {
    const int* w = (const int*)edge_index;
    int all_zero = 1;
    #pragma unroll
    for (int i = 1; i < 128; i += 2) all_zero &= (w[i] == 0);
    return all_zero;
}

// red.global.add.v4 WITHOUT a memory clobber: fire-and-forget atomic; register
// deps keep it correct and the compiler can overlap subsequent loads.
__device__ __forceinline__ void red_add_v4(float* dst, float4 v) {
    asm volatile("red.global.add.v4.f32 [%0], {%1,%2,%3,%4};"
                 :: "l"(dst), "f"(v.x), "f"(v.y), "f"(v.z), "f"(v.w));
}
// streaming (evict-first) float4 load — keeps the one-shot edge stream out of L2
__device__ __forceinline__ float4 ldcs4(const float4* p) {
    float4 v;
    asm volatile("ld.global.cs.v4.f32 {%0,%1,%2,%3}, [%4];"
                 : "=f"(v.x), "=f"(v.y), "=f"(v.z), "=f"(v.w) : "l"(p));
    return v;
}

// ---------------------------------------------------------------------------
// K1: blocks 0..EB-1 -> edge scatter (4 edges/iter, parallel index chains)
//     blocks EB..    -> node mean (block per graph, self-computed bounds)
// ---------------------------------------------------------------------------
__global__ void __launch_bounds__(256) edgenode_kernel(
        const float* __restrict__ edge_attr,
        const float* __restrict__ x,
        const void* __restrict__ edge_index,
        const void* __restrict__ batch,
        int n_edges, int n_nodes) {
    int b = blockIdx.x, tid = threadIdx.x;
    int lane = tid & 31;

    if (b < EB) {
        __shared__ int s_idx64;
        if (tid == 0) s_idx64 = probe_idx64(edge_index);
        __syncthreads();
        int idx64 = s_idx64;

        int warp_g = (b * 256 + tid) >> 5;
        int nwarps = (EB * 256) >> 5;
        int stride = nwarps * 4;
        int rep    = warp_g & (NREP - 1);
        const float4* ea = (const float4*)edge_attr;

        // lanes 0..3 each own one index chain per 4-edge batch
        int e = warp_g * 4;
        int gcur = 0;
        if (lane < 4 && e + lane < n_edges) {
            int src = load_idx(edge_index, e + lane, idx64);
            gcur = load_idx(batch, src, idx64);
        }

        for (; e < n_edges; e += stride) {
            // prefetch next batch's graph ids (independent chains)
            int en = e + stride;
            int gnxt = 0;
            if (lane < 4 && en + lane < n_edges) {
                int src = load_idx(edge_index, en + lane, idx64);
                gnxt = load_idx(batch, src, idx64);
            }

            int g0 = __shfl_sync(0xffffffffu, gcur, 0);
            int g1 = __shfl_sync(0xffffffffu, gcur, 1);
            int g2 = __shfl_sync(0xffffffffu, gcur, 2);
            int g3 = __shfl_sync(0xffffffffu, gcur, 3);

            // 4 independent streaming row loads
            float4 v0, v1, v2, v3;
            int h1 = (e + 1 < n_edges), h2 = (e + 2 < n_edges), h3 = (e + 3 < n_edges);
            v0 = ldcs4(&ea[(size_t)e * 32 + lane]);
            v1 = h1 ? ldcs4(&ea[(size_t)(e + 1) * 32 + lane]) : make_float4(0, 0, 0, 0);
            v2 = h2 ? ldcs4(&ea[(size_t)(e + 2) * 32 + lane]) : make_float4(0, 0, 0, 0);
            v3 = h3 ? ldcs4(&ea[(size_t)(e + 3) * 32 + lane]) : make_float4(0, 0, 0, 0);

            red_add_v4(d_escratch + ((size_t)rep * NG + g0) * DIM + lane * 4, v0);
            if (h1) red_add_v4(d_escratch + ((size_t)rep * NG + g1) * DIM + lane * 4, v1);
            if (h2) red_add_v4(d_escratch + ((size_t)rep * NG + g2) * DIM + lane * 4, v2);
            if (h3) red_add_v4(d_escratch + ((size_t)rep * NG + g3) * DIM + lane * 4, v3);

            // lane-parallel edge counts (lane i holds g_i)
            if (lane < 4 && e + lane < n_edges)
                atomicAdd(&d_ecnt[rep * NG + gcur], 1u);

            gcur = gnxt;
        }
    } else {
        // node mean: graph g's rows are contiguous in x (batch is sorted)
        int g = b - EB;
        __shared__ int s_bound[2];
        if (tid < 2) {
            int idx64 = probe_idx64(edge_index);
            int target = g + tid;
            int lo = 0, hi = n_nodes;
            while (lo < hi) {
                int m = (lo + hi) >> 1;
                if (load_idx(batch, m, idx64) < target) lo = m + 1; else hi = m;
            }
            s_bound[tid] = lo;
        }
        __syncthreads();
        int s = s_bound[0], e = s_bound[1];
        int cnt = e - s;
        int w = tid >> 5;

        const float4* xr = (const float4*)x;
        float4 acc = make_float4(0.f, 0.f, 0.f, 0.f);
        for (int n = s + w; n < e; n += 8) {
            float4 v = ldcs4(&xr[(size_t)n * 32 + lane]);
            acc.x += v.x; acc.y += v.y; acc.z += v.z; acc.w += v.w;
        }
        __shared__ float4 s_red[8][32];
        s_red[w][lane] = acc;
        __syncthreads();
        if (w == 0) {
            float4 t = s_red[0][lane];
            #pragma unroll
            for (int i = 1; i < 8; i++) {
                float4 q = s_red[i][lane];
                t.x += q.x; t.y += q.y; t.z += q.z; t.w += q.w;
            }
            float inv = 1.0f / (float)(cnt > 0 ? cnt : 1);
            t.x *= inv; t.y *= inv; t.z *= inv; t.w *= inv;
            ((float4*)(d_node_mean + (size_t)g * DIM))[lane] = t;
        }
    }
}

// ---------------------------------------------------------------------------
// K2 (mlp1): h = relu(inp @ W1 + b1), W1 staged in smem.
// 256 blocks = 16 col-slices (32 cols) x 16 graph-tiles (64 graphs).
// 256 threads: tx = tid&7 -> 4 cols, ty = tid>>3 -> 2 graphs. 6 k-chunks of 64.
// ---------------------------------------------------------------------------
__global__ void __launch_bounds__(256) mlp1_kernel(
        const float* __restrict__ u,
        const float* __restrict__ W1, const float* __restrict__ b1) {
    __shared__ float w1c[64 * 32];        // 8 KB: W1 chunk [64 k][32 cols]
    __shared__ float inps[64 * 65];       // 16.6 KB: inp [64 g][64 k + pad]
    __shared__ float s_inv[64];           // 1/edge_count per graph

    int bI = blockIdx.x;
    int sl = bI & 15;          // col slice (32 cols)
    int tI = bI >> 4;          // graph tile (64 graphs)
    int gbase = tI * 64;
    int tid = threadIdx.x;
    int tx = tid & 7, ty = tid >> 3;

    if (tid < 64) {
        unsigned c = 0;
        #pragma unroll
        for (int r = 0; r < NREP; r++) c += d_ecnt[r * NG + gbase + tid];
        s_inv[tid] = 1.0f / (float)(c > 0u ? c : 1u);
    }

    float4 bb = *(const float4*)&b1[sl * 32 + tx * 4];
    float acc[2][4];
    #pragma unroll
    for (int gi = 0; gi < 2; gi++) {
        acc[gi][0] = bb.x; acc[gi][1] = bb.y; acc[gi][2] = bb.z; acc[gi][3] = bb.w;
    }

    for (int ch = 0; ch < 6; ch++) {
        int kc = ch * 64;
        __syncthreads();   // protect smem from previous chunk's readers

        // stage W1 chunk [64 rows][32 cols]: 512 float4, 2 per thread
        #pragma unroll
        for (int p = 0; p < 2; p++) {
            int idx = tid + p * 256;
            int row = idx >> 3, cc = idx & 7;
            *(float4*)&w1c[row * 32 + cc * 4] =
                *(const float4*)&W1[(size_t)(kc + row) * HID + sl * 32 + cc * 4];
        }
        // stage inp chunk [64 graphs][64 features]: 1024 float4
        #pragma unroll
        for (int p = 0; p < 4; p++) {
            int idx = tid + p * 256;
            int g = idx >> 4, kq = idx & 15;
            int gg = gbase + g;
            float4 v;
            if (ch < 2) {
                v = *(const float4*)&u[(size_t)gg * DIM + kc + kq * 4];
            } else if (ch < 4) {
                int col = kc - 128 + kq * 4;
                v = make_float4(0.f, 0.f, 0.f, 0.f);
                #pragma unroll
                for (int r = 0; r < NREP; r++) {
                    float4 q = *(const float4*)&d_escratch[((size_t)r * NG + gg) * DIM + col];
                    v.x += q.x; v.y += q.y; v.z += q.z; v.w += q.w;
                }
                float iv = s_inv[g];
                v.x *= iv; v.y *= iv; v.z *= iv; v.w *= iv;
            } else {
                v = *(const float4*)&d_node_mean[(size_t)gg * DIM + kc - 256 + kq * 4];
            }
            float* dst = &inps[g * 65 + kq * 4];
            dst[0] = v.x; dst[1] = v.y; dst[2] = v.z; dst[3] = v.w;
        }
        __syncthreads();

        #pragma unroll 4
        for (int kk = 0; kk < 64; kk++) {
            float4 wv = *(const float4*)&w1c[kk * 32 + tx * 4];
            float x0 = inps[(ty * 2 + 0) * 65 + kk];
            float x1 = inps[(ty * 2 + 1) * 65 + kk];
            acc[0][0] = fmaf(x0, wv.x, acc[0][0]); acc[0][1] = fmaf(x0, wv.y, acc[0][1]);
            acc[0][2] = fmaf(x0, wv.z, acc[0][2]); acc[0][3] = fmaf(x0, wv.w, acc[0][3]);
            acc[1][0] = fmaf(x1, wv.x, acc[1][0]); acc[1][1] = fmaf(x1, wv.y, acc[1][1]);
            acc[1][2] = fmaf(x1, wv.z, acc[1][2]); acc[1][3] = fmaf(x1, wv.w, acc[1][3]);
        }
    }

    // write h with relu (float4)
    #pragma unroll
    for (int gi = 0; gi < 2; gi++) {
        int gg = gbase + ty * 2 + gi;
        float4 o;
        o.x = fmaxf(acc[gi][0], 0.f); o.y = fmaxf(acc[gi][1], 0.f);
        o.z = fmaxf(acc[gi][2], 0.f); o.w = fmaxf(acc[gi][3], 0.f);
        *(float4*)&d_hbuf[(size_t)gg * HID + sl * 32 + tx * 4] = o;
    }
}

// ---------------------------------------------------------------------------
// K3 (mlp2): y = LayerNorm(h @ W2 + b2 + u), W2 staged in smem.
// 128 blocks x 8 graphs, 256 threads; warp w owns graph w, lane owns 4 cols.
// 8 k-chunks of 64. Also re-zeroes scratch.
// ---------------------------------------------------------------------------
__global__ void __launch_bounds__(256) mlp2_kernel(
        const float* __restrict__ u,
        const float* __restrict__ W2, const float* __restrict__ b2,
        const float* __restrict__ gamma, const float* __restrict__ beta,
        float* __restrict__ out) {
    __shared__ float w2c[64 * 128];    // 32 KB: W2 chunk [64 k][128 cols]
    __shared__ float hs[8 * 64];       // 2 KB: h chunk [8 g][64 k]

    int bI = blockIdx.x;
    int gbase = bI * 8;
    int tid = threadIdx.x;
    int w = tid >> 5, lane = tid & 31;
    int c0 = lane * 4;

    float4 a = *(const float4*)&b2[c0];

    for (int ch = 0; ch < 8; ch++) {
        int kc = ch * 64;
        __syncthreads();
        // stage W2 chunk: 2048 float4, 8 per thread
        #pragma unroll
        for (int p = 0; p < 8; p++) {
            int idx = tid + p * 256;
            int row = idx >> 5, cg = idx & 31;
            *(float4*)&w2c[row * 128 + cg * 4] =
                *(const float4*)&W2[(size_t)(kc + row) * DIM + cg * 4];
        }
        // stage h chunk: 8 g x 16 float4 = 128 threads
        if (tid < 128) {
            int g = tid >> 4, kq = tid & 15;
            *(float4*)&hs[g * 64 + kq * 4] =
                *(const float4*)&d_hbuf[(size_t)(gbase + g) * HID + kc + kq * 4];
        }
        __syncthreads();

        #pragma unroll 4
        for (int kk = 0; kk < 64; kk++) {
            float hv = hs[w * 64 + kk];
            float4 wv = *(const float4*)&w2c[kk * 128 + c0];
            a.x = fmaf(hv, wv.x, a.x); a.y = fmaf(hv, wv.y, a.y);
            a.z = fmaf(hv, wv.z, a.z); a.w = fmaf(hv, wv.w, a.w);
        }
    }

    // residual + layernorm (warp w -> graph gbase+w)
    {
        int gg = gbase + w;
        float4 uu = *(const float4*)&u[(size_t)gg * DIM + c0];
        a.x += uu.x; a.y += uu.y; a.z += uu.z; a.w += uu.w;

        float sm = a.x + a.y + a.z + a.w;
        #pragma unroll
        for (int off = 16; off; off >>= 1) sm += __shfl_xor_sync(0xffffffffu, sm, off);
        float mu = sm * (1.0f / DIM);

        float dx = a.x - mu, dy = a.y - mu, dz = a.z - mu, dw = a.w - mu;
        float sq = dx * dx + dy * dy + dz * dz + dw * dw;
        #pragma unroll
        for (int off = 16; off; off >>= 1) sq += __shfl_xor_sync(0xffffffffu, sq, off);
        float rs = rsqrtf(sq * (1.0f / DIM) + 1e-5f);

        float4 gm = *(const float4*)&gamma[c0];
        float4 bt = *(const float4*)&beta[c0];
        float4 o;
        o.x = dx * rs * gm.x + bt.x;
        o.y = dy * rs * gm.y + bt.y;
        o.z = dz * rs * gm.z + bt.z;
        o.w = dw * rs * gm.w + bt.w;
        *(float4*)&out[(size_t)gg * DIM + c0] = o;
    }

    // re-zero the edge scratch + counts (safe: all mlp1 reads are done)
    {
        float4 z = make_float4(0.f, 0.f, 0.f, 0.f);
        // NREP*NG*DIM floats = 1048576 float4 over 128 blocks = 8192 each
        #pragma unroll
        for (int p = 0; p < 32; p++)
            ((float4*)d_escratch)[bI * 8192 + p * 256 + tid] = z;
        // NREP*NG = 32768 counters over 128 blocks = 256 each
        d_ecnt[bI * 256 + tid] = 0u;
    }
}

// ---------------------------------------------------------------------------
extern "C" void kernel_launch(void* const* d_in, const int* in_sizes, int n_in,
                              void* d_out, int out_size) {
    const float* x         = (const float*)d_in[0];
    const float* edge_attr = (const float*)d_in[1];
    const float* u         = (const float*)d_in[2];
    const float* W1        = (const float*)d_in[3];
    const float* b1        = (const float*)d_in[4];
    const float* W2        = (const float*)d_in[5];
    const float* b2        = (const float*)d_in[6];
    const float* gamma     = (const float*)d_in[7];
    const float* beta      = (const float*)d_in[8];
    const void* edge_index = d_in[9];
    const void* batch      = d_in[10];

    int n_edges = in_sizes[9] / 2;
    int n_nodes = in_sizes[10];
    float* out = (float*)d_out;

    edgenode_kernel<<<EB + NG, 256>>>(edge_attr, x, edge_index, batch,
                                      n_edges, n_nodes);                   // 1
    mlp1_kernel<<<256, 256>>>(u, W1, b1);                                  // 2
    mlp2_kernel<<<128, 256>>>(u, W2, b2, gamma, beta, out);                // 3
}

// round 15
// speedup vs baseline: 1.0228x; 1.0228x over previous
#include <cuda_runtime.h>
#include <cstdint>

#define NG    1024
#define DIM   128
#define HID   512
#define NREP  32
#define EB    1184     // edge blocks in fused kernel

// ---- scratch (no allocations allowed) ----
// Zero-initialized at load; reduce_kernel re-zeroes in-place after consuming,
// so every kernel_launch call observes zeroed scratch (graph-replay safe).
__device__ float    d_escratch[NREP * NG * DIM];   // 16 MB replicated edge sums
__device__ unsigned d_ecnt[NREP * NG];             // replicated edge counts
__device__ float    d_edge_mean[NG * DIM];
__device__ float    d_node_mean[NG * DIM];
__device__ float    d_hbuf[NG * HID];              // hidden activations (2 MB)

// ---------------------------------------------------------------------------
__device__ __forceinline__ int load_idx(const void* p, long long i, int idx64) {
    return idx64 ? (int)((const long long*)p)[i] : ((const int*)p)[i];
}
// dtype probe on edge_index: node ids are random nonzero ints, so
// all-zero odd 32-bit words <=> int64 storage.
__device__ __forceinline__ int probe_idx64(const void* edge_index) {
    const int* w = (const int*)edge_index;
    int all_zero = 1;
    #pragma unroll
    for (int i = 1; i < 128; i += 2) all_zero &= (w[i] == 0);
    return all_zero;
}

// red.global.add.v4 WITHOUT a memory clobber: fire-and-forget atomic; register
// deps keep it correct and the compiler can overlap subsequent loads.
__device__ __forceinline__ void red_add_v4(float* dst, float4 v) {
    asm volatile("red.global.add.v4.f32 [%0], {%1,%2,%3,%4};"
                 :: "l"(dst), "f"(v.x), "f"(v.y), "f"(v.z), "f"(v.w));
}
// streaming (evict-first) float4 load — keeps the one-shot edge stream out of L2
__device__ __forceinline__ float4 ldcs4(const float4* p) {
    float4 v;
    asm volatile("ld.global.cs.v4.f32 {%0,%1,%2,%3}, [%4];"
                 : "=f"(v.x), "=f"(v.y), "=f"(v.z), "=f"(v.w) : "l"(p));
    return v;
}

// ---------------------------------------------------------------------------
// K1: blocks 0..EB-1 -> edge scatter (4 edges/iter, parallel index chains)
//     blocks EB..    -> node mean (block per graph, self-computed bounds)
// ---------------------------------------------------------------------------
__global__ void __launch_bounds__(256) edgenode_kernel(
        const float* __restrict__ edge_attr,
        const float* __restrict__ x,
        const void* __restrict__ edge_index,
        const void* __restrict__ batch,
        int n_edges, int n_nodes) {
    int b = blockIdx.x, tid = threadIdx.x;
    int lane = tid & 31;

    if (b < EB) {
        __shared__ int s_idx64;
        if (tid == 0) s_idx64 = probe_idx64(edge_index);
        __syncthreads();
        int idx64 = s_idx64;

        int warp_g = (b * 256 + tid) >> 5;
        int nwarps = (EB * 256) >> 5;
        int stride = nwarps * 4;
        int rep    = warp_g & (NREP - 1);
        const float4* ea = (const float4*)edge_attr;

        // lanes 0..3 each own one index chain per 4-edge batch
        int e = warp_g * 4;
        int gcur = 0;
        if (lane < 4 && e + lane < n_edges) {
            int src = load_idx(edge_index, e + lane, idx64);
            gcur = load_idx(batch, src, idx64);
        }

        for (; e < n_edges; e += stride) {
            // prefetch next batch's graph ids (independent chains)
            int en = e + stride;
            int gnxt = 0;
            if (lane < 4 && en + lane < n_edges) {
                int src = load_idx(edge_index, en + lane, idx64);
                gnxt = load_idx(batch, src, idx64);
            }

            int g0 = __shfl_sync(0xffffffffu, gcur, 0);
            int g1 = __shfl_sync(0xffffffffu, gcur, 1);
            int g2 = __shfl_sync(0xffffffffu, gcur, 2);
            int g3 = __shfl_sync(0xffffffffu, gcur, 3);

            // 4 independent streaming row loads
            float4 v0, v1, v2, v3;
            int h1 = (e + 1 < n_edges), h2 = (e + 2 < n_edges), h3 = (e + 3 < n_edges);
            v0 = ldcs4(&ea[(size_t)e * 32 + lane]);
            v1 = h1 ? ldcs4(&ea[(size_t)(e + 1) * 32 + lane]) : make_float4(0, 0, 0, 0);
            v2 = h2 ? ldcs4(&ea[(size_t)(e + 2) * 32 + lane]) : make_float4(0, 0, 0, 0);
            v3 = h3 ? ldcs4(&ea[(size_t)(e + 3) * 32 + lane]) : make_float4(0, 0, 0, 0);

            red_add_v4(d_escratch + ((size_t)rep * NG + g0) * DIM + lane * 4, v0);
            if (h1) red_add_v4(d_escratch + ((size_t)rep * NG + g1) * DIM + lane * 4, v1);
            if (h2) red_add_v4(d_escratch + ((size_t)rep * NG + g2) * DIM + lane * 4, v2);
            if (h3) red_add_v4(d_escratch + ((size_t)rep * NG + g3) * DIM + lane * 4, v3);

            // lane-parallel edge counts (lane i holds g_i)
            if (lane < 4 && e + lane < n_edges)
                atomicAdd(&d_ecnt[rep * NG + gcur], 1u);

            gcur = gnxt;
        }
    } else {
        // node mean: graph g's rows are contiguous in x (batch is sorted)
        int g = b - EB;
        __shared__ int s_bound[2];
        if (tid < 2) {
            int idx64 = probe_idx64(edge_index);
            int target = g + tid;
            int lo = 0, hi = n_nodes;
            while (lo < hi) {
                int m = (lo + hi) >> 1;
                if (load_idx(batch, m, idx64) < target) lo = m + 1; else hi = m;
            }
            s_bound[tid] = lo;
        }
        __syncthreads();
        int s = s_bound[0], e = s_bound[1];
        int cnt = e - s;
        int w = tid >> 5;

        const float4* xr = (const float4*)x;
        float4 acc = make_float4(0.f, 0.f, 0.f, 0.f);
        for (int n = s + w; n < e; n += 8) {
            float4 v = ldcs4(&xr[(size_t)n * 32 + lane]);
            acc.x += v.x; acc.y += v.y; acc.z += v.z; acc.w += v.w;
        }
        __shared__ float4 s_red[8][32];
        s_red[w][lane] = acc;
        __syncthreads();
        if (w == 0) {
            float4 t = s_red[0][lane];
            #pragma unroll
            for (int i = 1; i < 8; i++) {
                float4 q = s_red[i][lane];
                t.x += q.x; t.y += q.y; t.z += q.z; t.w += q.w;
            }
            float inv = 1.0f / (float)(cnt > 0 ? cnt : 1);
            t.x *= inv; t.y *= inv; t.z *= inv; t.w *= inv;
            ((float4*)(d_node_mean + (size_t)g * DIM))[lane] = t;
        }
    }
}

// ---------------------------------------------------------------------------
// K2 (reduce): collapse 32 replicas -> d_edge_mean, zero scratch in place.
// 128 blocks x 256 threads; thread owns one float4 column (8 graphs/block).
// ---------------------------------------------------------------------------
__global__ void __launch_bounds__(256) reduce_kernel() {
    __shared__ float s_inv[8];
    int bI = blockIdx.x, tid = threadIdx.x;
    int gbase = bI * 8;                         // 8 graphs per block
    int idx = bI * 256 + tid;                   // float4 column id (32768 total)

    // counts: 8 graphs x 32 reps = 256 entries -> one per thread
    {
        int r = tid >> 3, gl = tid & 7;
        unsigned c = d_ecnt[r * NG + gbase + gl];
        d_ecnt[r * NG + gbase + gl] = 0u;
        // warp-level tree within the 8 entries of the same graph? simplest:
        // use shared atomic accumulation
        __shared__ unsigned s_cnt[8];
        if (tid < 8) s_cnt[tid] = 0u;
        __syncthreads();
        atomicAdd(&s_cnt[gl], c);
        __syncthreads();
        if (tid < 8) s_inv[tid] = 1.0f / (float)(s_cnt[tid] > 0u ? s_cnt[tid] : 1u);
        __syncthreads();
    }

    float4* es4 = (float4*)d_escratch;
    const int stride4 = NG * DIM / 4;           // 32768 float4 per replica
    float4 s = make_float4(0.f, 0.f, 0.f, 0.f);
    float4 z = make_float4(0.f, 0.f, 0.f, 0.f);
    #pragma unroll 8
    for (int r = 0; r < NREP; r++) {
        float4 q = es4[(size_t)r * stride4 + idx];
        s.x += q.x; s.y += q.y; s.z += q.z; s.w += q.w;
        es4[(size_t)r * stride4 + idx] = z;      // re-zero in place
    }
    float inv = s_inv[(tid >> 5)];               // graph = idx>>5 -> local (tid>>5)
    s.x *= inv; s.y *= inv; s.z *= inv; s.w *= inv;
    ((float4*)d_edge_mean)[idx] = s;
}

// ---------------------------------------------------------------------------
// K3 (mlp1): h = relu(inp @ W1 + b1), W1 staged in smem.
// 256 blocks = 16 col-slices (32 cols) x 16 graph-tiles (64 graphs).
// 256 threads: tx = tid&7 -> 4 cols, ty = tid>>3 -> 2 graphs. 6 k-chunks of 64.
// ---------------------------------------------------------------------------
__global__ void __launch_bounds__(256) mlp1_kernel(
        const float* __restrict__ u,
        const float* __restrict__ W1, const float* __restrict__ b1) {
    __shared__ float w1c[64 * 32];        // 8 KB: W1 chunk [64 k][32 cols]
    __shared__ float inps[64 * 65];       // 16.6 KB: inp [64 g][64 k + pad]

    int bI = blockIdx.x;
    int sl = bI & 15;          // col slice (32 cols)
    int tI = bI >> 4;          // graph tile (64 graphs)
    int gbase = tI * 64;
    int tid = threadIdx.x;
    int tx = tid & 7, ty = tid >> 3;

    float4 bb = *(const float4*)&b1[sl * 32 + tx * 4];
    float acc[2][4];
    #pragma unroll
    for (int gi = 0; gi < 2; gi++) {
        acc[gi][0] = bb.x; acc[gi][1] = bb.y; acc[gi][2] = bb.z; acc[gi][3] = bb.w;
    }

    for (int ch = 0; ch < 6; ch++) {
        int kc = ch * 64;
        __syncthreads();   // protect smem from previous chunk's readers

        // stage W1 chunk [64 rows][32 cols]: 512 float4, 2 per thread
        #pragma unroll
        for (int p = 0; p < 2; p++) {
            int idx = tid + p * 256;
            int row = idx >> 3, cc = idx & 7;
            *(float4*)&w1c[row * 32 + cc * 4] =
                *(const float4*)&W1[(size_t)(kc + row) * HID + sl * 32 + cc * 4];
        }
        // stage inp chunk [64 graphs][64 features]: 1024 float4
        #pragma unroll
        for (int p = 0; p < 4; p++) {
            int idx = tid + p * 256;
            int g = idx >> 4, kq = idx & 15;
            int gg = gbase + g;
            float4 v;
            if (ch < 2) {
                v = *(const float4*)&u[(size_t)gg * DIM + kc + kq * 4];
            } else if (ch < 4) {
                v = *(const float4*)&d_edge_mean[(size_t)gg * DIM + kc - 128 + kq * 4];
            } else {
                v = *(const float4*)&d_node_mean[(size_t)gg * DIM + kc - 256 + kq * 4];
            }
            float* dst = &inps[g * 65 + kq * 4];
            dst[0] = v.x; dst[1] = v.y; dst[2] = v.z; dst[3] = v.w;
        }
        __syncthreads();

        #pragma unroll 4
        for (int kk = 0; kk < 64; kk++) {
            float4 wv = *(const float4*)&w1c[kk * 32 + tx * 4];
            float x0 = inps[(ty * 2 + 0) * 65 + kk];
            float x1 = inps[(ty * 2 + 1) * 65 + kk];
            acc[0][0] = fmaf(x0, wv.x, acc[0][0]); acc[0][1] = fmaf(x0, wv.y, acc[0][1]);
            acc[0][2] = fmaf(x0, wv.z, acc[0][2]); acc[0][3] = fmaf(x0, wv.w, acc[0][3]);
            acc[1][0] = fmaf(x1, wv.x, acc[1][0]); acc[1][1] = fmaf(x1, wv.y, acc[1][1]);
            acc[1][2] = fmaf(x1, wv.z, acc[1][2]); acc[1][3] = fmaf(x1, wv.w, acc[1][3]);
        }
    }

    // write h with relu (float4)
    #pragma unroll
    for (int gi = 0; gi < 2; gi++) {
        int gg = gbase + ty * 2 + gi;
        float4 o;
        o.x = fmaxf(acc[gi][0], 0.f); o.y = fmaxf(acc[gi][1], 0.f);
        o.z = fmaxf(acc[gi][2], 0.f); o.w = fmaxf(acc[gi][3], 0.f);
        *(float4*)&d_hbuf[(size_t)gg * HID + sl * 32 + tx * 4] = o;
    }
}

// ---------------------------------------------------------------------------
// K4 (mlp2): y = LayerNorm(h @ W2 + b2 + u), W2 staged in smem.
// 128 blocks x 8 graphs, 256 threads; warp w owns graph w, lane owns 4 cols.
// ---------------------------------------------------------------------------
__global__ void __launch_bounds__(256) mlp2_kernel(
        const float* __restrict__ u,
        const float* __restrict__ W2, const float* __restrict__ b2,
        const float* __restrict__ gamma, const float* __restrict__ beta,
        float* __restrict__ out) {
    __shared__ float w2c[64 * 128];    // 32 KB: W2 chunk [64 k][128 cols]
    __shared__ float hs[8 * 64];       // 2 KB: h chunk [8 g][64 k]

    int bI = blockIdx.x;
    int gbase = bI * 8;
    int tid = threadIdx.x;
    int w = tid >> 5, lane = tid & 31;
    int c0 = lane * 4;

    float4 a = *(const float4*)&b2[c0];

    for (int ch = 0; ch < 8; ch++) {
        int kc = ch * 64;
        __syncthreads();
        // stage W2 chunk: 2048 float4, 8 per thread
        #pragma unroll
        for (int p = 0; p < 8; p++) {
            int idx = tid + p * 256;
            int row = idx >> 5, cg = idx & 31;
            *(float4*)&w2c[row * 128 + cg * 4] =
                *(const float4*)&W2[(size_t)(kc + row) * DIM + cg * 4];
        }
        // stage h chunk: 8 g x 16 float4 = 128 threads
        if (tid < 128) {
            int g = tid >> 4, kq = tid & 15;
            *(float4*)&hs[g * 64 + kq * 4] =
                *(const float4*)&d_hbuf[(size_t)(gbase + g) * HID + kc + kq * 4];
        }
        __syncthreads();

        #pragma unroll 4
        for (int kk = 0; kk < 64; kk++) {
            float hv = hs[w * 64 + kk];
            float4 wv = *(const float4*)&w2c[kk * 128 + c0];
            a.x = fmaf(hv, wv.x, a.x); a.y = fmaf(hv, wv.y, a.y);
            a.z = fmaf(hv, wv.z, a.z); a.w = fmaf(hv, wv.w, a.w);
        }
    }

    // residual + layernorm (warp w -> graph gbase+w)
    {
        int gg = gbase + w;
        float4 uu = *(const float4*)&u[(size_t)gg * DIM + c0];
        a.x += uu.x; a.y += uu.y; a.z += uu.z; a.w += uu.w;

        float sm = a.x + a.y + a.z + a.w;
        #pragma unroll
        for (int off = 16; off; off >>= 1) sm += __shfl_xor_sync(0xffffffffu, sm, off);
        float mu = sm * (1.0f / DIM);

        float dx = a.x - mu, dy = a.y - mu, dz = a.z - mu, dw = a.w - mu;
        float sq = dx * dx + dy * dy + dz * dz + dw * dw;
        #pragma unroll
        for (int off = 16; off; off >>= 1) sq += __shfl_xor_sync(0xffffffffu, sq, off);
        float rs = rsqrtf(sq * (1.0f / DIM) + 1e-5f);

        float4 gm = *(const float4*)&gamma[c0];
        float4 bt = *(const float4*)&beta[c0];
        float4 o;
        o.x = dx * rs * gm.x + bt.x;
        o.y = dy * rs * gm.y + bt.y;
        o.z = dz * rs * gm.z + bt.z;
        o.w = dw * rs * gm.w + bt.w;
        *(float4*)&out[(size_t)gg * DIM + c0] = o;
    }
}

// ---------------------------------------------------------------------------
extern "C" void kernel_launch(void* const* d_in, const int* in_sizes, int n_in,
                              void* d_out, int out_size) {
    const float* x         = (const float*)d_in[0];
    const float* edge_attr = (const float*)d_in[1];
    const float* u         = (const float*)d_in[2];
    const float* W1        = (const float*)d_in[3];
    const float* b1        = (const float*)d_in[4];
    const float* W2        = (const float*)d_in[5];
    const float* b2        = (const float*)d_in[6];
    const float* gamma     = (const float*)d_in[7];
    const float* beta      = (const float*)d_in[8];
    const void* edge_index = d_in[9];
    const void* batch      = d_in[10];

    int n_edges = in_sizes[9] / 2;
    int n_nodes = in_sizes[10];
    float* out = (float*)d_out;

    edgenode_kernel<<<EB + NG, 256>>>(edge_attr, x, edge_index, batch,
                                      n_edges, n_nodes);                   // 1
    reduce_kernel<<<128, 256>>>();                                         // 2
    mlp1_kernel<<<256, 256>>>(u, W1, b1);                                  // 3
    mlp2_kernel<<<128, 256>>>(u, W2, b2, gamma, beta, out);                // 4
}

// round 16
// speedup vs baseline: 1.2353x; 1.2078x over previous
#include <cuda_runtime.h>
#include <cstdint>

#define NG    1024
#define DIM   128
#define HID   512
#define NREP  16
#define EB    1184     // edge blocks in fused kernel

// ---- scratch (no allocations allowed) ----
// Zero-initialized at load; reduce_kernel re-zeroes in-place after consuming,
// so every kernel_launch call observes zeroed scratch (graph-replay safe).
__device__ float    d_escratch[NREP * NG * DIM];   // 8 MB replicated edge sums
__device__ unsigned d_ecnt[NREP * NG];             // replicated edge counts
__device__ float    d_edge_mean[NG * DIM];
__device__ float    d_node_mean[NG * DIM];
__device__ float    d_hbuf[NG * HID];              // hidden activations (2 MB)

// ---------------------------------------------------------------------------
__device__ __forceinline__ int load_idx(const void* p, long long i, int idx64) {
    return idx64 ? (int)((const long long*)p)[i] : ((const int*)p)[i];
}
// dtype probe on edge_index: node ids are random nonzero ints, so
// all-zero odd 32-bit words <=> int64 storage.
__device__ __forceinline__ int probe_idx64(const void* edge_index) {
    const int* w = (const int*)edge_index;
    int all_zero = 1;
    #pragma unroll
    for (int i = 1; i < 128; i += 2) all_zero &= (w[i] == 0);
    return all_zero;
}

// red.global.add.v4 WITHOUT a memory clobber: fire-and-forget atomic; register
// deps keep it correct and the compiler can overlap subsequent loads.
__device__ __forceinline__ void red_add_v4(float* dst, float4 v) {
    asm volatile("red.global.add.v4.f32 [%0], {%1,%2,%3,%4};"
                 :: "l"(dst), "f"(v.x), "f"(v.y), "f"(v.z), "f"(v.w));
}

// ---------------------------------------------------------------------------
// K1: blocks 0..EB-1 -> edge scatter (4 edges/iter, parallel index chains)
//     blocks EB..    -> node mean (block per graph, self-computed bounds)
// Plain (default-policy) loads everywhere: graph replays re-read edge_attr/x,
// and L2 retention across replays matters more than cold-run behavior.
// ---------------------------------------------------------------------------
__global__ void __launch_bounds__(256) edgenode_kernel(
        const float* __restrict__ edge_attr,
        const float* __restrict__ x,
        const void* __restrict__ edge_index,
        const void* __restrict__ batch,
        int n_edges, int n_nodes) {
    int b = blockIdx.x, tid = threadIdx.x;
    int lane = tid & 31;

    if (b < EB) {
        __shared__ int s_idx64;
        if (tid == 0) s_idx64 = probe_idx64(edge_index);
        __syncthreads();
        int idx64 = s_idx64;

        int warp_g = (b * 256 + tid) >> 5;
        int nwarps = (EB * 256) >> 5;
        int stride = nwarps * 4;
        int rep    = warp_g & (NREP - 1);
        const float4* ea = (const float4*)edge_attr;

        // lanes 0..3 each own one index chain per 4-edge batch
        int e = warp_g * 4;
        int gcur = 0;
        if (lane < 4 && e + lane < n_edges) {
            int src = load_idx(edge_index, e + lane, idx64);
            gcur = load_idx(batch, src, idx64);
        }

        for (; e < n_edges; e += stride) {
            // prefetch next batch's graph ids (independent chains)
            int en = e + stride;
            int gnxt = 0;
            if (lane < 4 && en + lane < n_edges) {
                int src = load_idx(edge_index, en + lane, idx64);
                gnxt = load_idx(batch, src, idx64);
            }

            int g0 = __shfl_sync(0xffffffffu, gcur, 0);
            int g1 = __shfl_sync(0xffffffffu, gcur, 1);
            int g2 = __shfl_sync(0xffffffffu, gcur, 2);
            int g3 = __shfl_sync(0xffffffffu, gcur, 3);

            // 4 independent row loads
            float4 v0, v1, v2, v3;
            int h1 = (e + 1 < n_edges), h2 = (e + 2 < n_edges), h3 = (e + 3 < n_edges);
            v0 = ea[(size_t)e * 32 + lane];
            v1 = h1 ? ea[(size_t)(e + 1) * 32 + lane] : make_float4(0, 0, 0, 0);
            v2 = h2 ? ea[(size_t)(e + 2) * 32 + lane] : make_float4(0, 0, 0, 0);
            v3 = h3 ? ea[(size_t)(e + 3) * 32 + lane] : make_float4(0, 0, 0, 0);

            red_add_v4(d_escratch + ((size_t)rep * NG + g0) * DIM + lane * 4, v0);
            if (h1) red_add_v4(d_escratch + ((size_t)rep * NG + g1) * DIM + lane * 4, v1);
            if (h2) red_add_v4(d_escratch + ((size_t)rep * NG + g2) * DIM + lane * 4, v2);
            if (h3) red_add_v4(d_escratch + ((size_t)rep * NG + g3) * DIM + lane * 4, v3);

            // lane-parallel edge counts (lane i holds g_i)
            if (lane < 4 && e + lane < n_edges)
                atomicAdd(&d_ecnt[rep * NG + gcur], 1u);

            gcur = gnxt;
        }
    } else {
        // node mean: graph g's rows are contiguous in x (batch is sorted)
        int g = b - EB;
        __shared__ int s_bound[2];
        if (tid < 2) {
            int idx64 = probe_idx64(edge_index);
            int target = g + tid;
            int lo = 0, hi = n_nodes;
            while (lo < hi) {
                int m = (lo + hi) >> 1;
                if (load_idx(batch, m, idx64) < target) lo = m + 1; else hi = m;
            }
            s_bound[tid] = lo;
        }
        __syncthreads();
        int s = s_bound[0], e = s_bound[1];
        int cnt = e - s;
        int w = tid >> 5;

        const float4* xr = (const float4*)x;
        float4 acc = make_float4(0.f, 0.f, 0.f, 0.f);
        for (int n = s + w; n < e; n += 8) {
            float4 v = xr[(size_t)n * 32 + lane];
            acc.x += v.x; acc.y += v.y; acc.z += v.z; acc.w += v.w;
        }
        __shared__ float4 s_red[8][32];
        s_red[w][lane] = acc;
        __syncthreads();
        if (w == 0) {
            float4 t = s_red[0][lane];
            #pragma unroll
            for (int i = 1; i < 8; i++) {
                float4 q = s_red[i][lane];
                t.x += q.x; t.y += q.y; t.z += q.z; t.w += q.w;
            }
            float inv = 1.0f / (float)(cnt > 0 ? cnt : 1);
            t.x *= inv; t.y *= inv; t.z *= inv; t.w *= inv;
            ((float4*)(d_node_mean + (size_t)g * DIM))[lane] = t;
        }
    }
}

// ---------------------------------------------------------------------------
// K2 (reduce): 1024 blocks (one graph each) x 128 threads.
// Coalesced replica reduce + in-place zero; trivially parallel.
// ---------------------------------------------------------------------------
__global__ void __launch_bounds__(128) reduce_kernel() {
    __shared__ unsigned sc[NREP];
    __shared__ float s_inv;
    int g = blockIdx.x, t = threadIdx.x;

    if (t < NREP) {
        sc[t] = d_ecnt[t * NG + g];
        d_ecnt[t * NG + g] = 0u;
    }
    __syncthreads();
    if (t == 0) {
        unsigned c = 0;
        #pragma unroll
        for (int r = 0; r < NREP; r++) c += sc[r];
        s_inv = 1.0f / (float)(c > 0u ? c : 1u);
    }
    __syncthreads();

    float s = 0.f;
    #pragma unroll
    for (int r = 0; r < NREP; r++) {
        size_t off = ((size_t)r * NG + g) * DIM + t;
        s += d_escratch[off];
        d_escratch[off] = 0.f;
    }
    d_edge_mean[(size_t)g * DIM + t] = s * s_inv;
}

// ---------------------------------------------------------------------------
// K3 (mlp1): h = relu(inp @ W1 + b1), W1 staged in smem.
// 256 blocks = 16 col-slices (32 cols) x 16 graph-tiles (64 graphs).
// ---------------------------------------------------------------------------
__global__ void __launch_bounds__(256) mlp1_kernel(
        const float* __restrict__ u,
        const float* __restrict__ W1, const float* __restrict__ b1) {
    __shared__ float w1c[64 * 32];        // 8 KB: W1 chunk [64 k][32 cols]
    __shared__ float inps[64 * 65];       // 16.6 KB: inp [64 g][64 k + pad]

    int bI = blockIdx.x;
    int sl = bI & 15;          // col slice (32 cols)
    int tI = bI >> 4;          // graph tile (64 graphs)
    int gbase = tI * 64;
    int tid = threadIdx.x;
    int tx = tid & 7, ty = tid >> 3;

    float4 bb = *(const float4*)&b1[sl * 32 + tx * 4];
    float acc[2][4];
    #pragma unroll
    for (int gi = 0; gi < 2; gi++) {
        acc[gi][0] = bb.x; acc[gi][1] = bb.y; acc[gi][2] = bb.z; acc[gi][3] = bb.w;
    }

    for (int ch = 0; ch < 6; ch++) {
        int kc = ch * 64;
        __syncthreads();   // protect smem from previous chunk's readers

        // stage W1 chunk [64 rows][32 cols]: 512 float4, 2 per thread
        #pragma unroll
        for (int p = 0; p < 2; p++) {
            int idx = tid + p * 256;
            int row = idx >> 3, cc = idx & 7;
            *(float4*)&w1c[row * 32 + cc * 4] =
                *(const float4*)&W1[(size_t)(kc + row) * HID + sl * 32 + cc * 4];
        }
        // stage inp chunk [64 graphs][64 features]: 1024 float4
        #pragma unroll
        for (int p = 0; p < 4; p++) {
            int idx = tid + p * 256;
            int g = idx >> 4, kq = idx & 15;
            int gg = gbase + g;
            float4 v;
            if (ch < 2) {
                v = *(const float4*)&u[(size_t)gg * DIM + kc + kq * 4];
            } else if (ch < 4) {
                v = *(const float4*)&d_edge_mean[(size_t)gg * DIM + kc - 128 + kq * 4];
            } else {
                v = *(const float4*)&d_node_mean[(size_t)gg * DIM + kc - 256 + kq * 4];
            }
            float* dst = &inps[g * 65 + kq * 4];
            dst[0] = v.x; dst[1] = v.y; dst[2] = v.z; dst[3] = v.w;
        }
        __syncthreads();

        #pragma unroll 4
        for (int kk = 0; kk < 64; kk++) {
            float4 wv = *(const float4*)&w1c[kk * 32 + tx * 4];
            float x0 = inps[(ty * 2 + 0) * 65 + kk];
            float x1 = inps[(ty * 2 + 1) * 65 + kk];
            acc[0][0] = fmaf(x0, wv.x, acc[0][0]); acc[0][1] = fmaf(x0, wv.y, acc[0][1]);
            acc[0][2] = fmaf(x0, wv.z, acc[0][2]); acc[0][3] = fmaf(x0, wv.w, acc[0][3]);
            acc[1][0] = fmaf(x1, wv.x, acc[1][0]); acc[1][1] = fmaf(x1, wv.y, acc[1][1]);
            acc[1][2] = fmaf(x1, wv.z, acc[1][2]); acc[1][3] = fmaf(x1, wv.w, acc[1][3]);
        }
    }

    // write h with relu (float4)
    #pragma unroll
    for (int gi = 0; gi < 2; gi++) {
        int gg = gbase + ty * 2 + gi;
        float4 o;
        o.x = fmaxf(acc[gi][0], 0.f); o.y = fmaxf(acc[gi][1], 0.f);
        o.z = fmaxf(acc[gi][2], 0.f); o.w = fmaxf(acc[gi][3], 0.f);
        *(float4*)&d_hbuf[(size_t)gg * HID + sl * 32 + tx * 4] = o;
    }
}

// ---------------------------------------------------------------------------
// K4 (mlp2): y = LayerNorm(h @ W2 + b2 + u).
// 256 blocks x 4 graphs, 512 threads. h staged once; W2 in 32-row chunks with
// register double-buffering (load next chunk while computing current).
// ---------------------------------------------------------------------------
__global__ void __launch_bounds__(512) mlp2_kernel(
        const float* __restrict__ u,
        const float* __restrict__ W2, const float* __restrict__ b2,
        const float* __restrict__ gamma, const float* __restrict__ beta,
        float* __restrict__ out) {
    __shared__ float hbufs[4][HID];    // 8 KB: full h rows for 4 graphs
    __shared__ float w2c[32 * 128];    // 16 KB: W2 chunk [32 k][128 cols]
    __shared__ float ysm[4][DIM];      // 2 KB

    int bI = blockIdx.x;
    int gbase = bI * 4;
    int tid = threadIdx.x;
    int g = tid >> 7;           // 0..3
    int c = tid & 127;          // output col

    // stage h fully: 4 x 512 floats = 512 float4, one per thread
    {
        int gi = tid >> 7, k4 = tid & 127;
        *(float4*)&hbufs[gi][k4 * 4] =
            *(const float4*)&d_hbuf[(size_t)(gbase + gi) * HID + k4 * 4];
    }

    // chunk staging: 32 rows x 128 cols = 1024 float4; 512 threads -> 2 each
    int srow0 = (tid * 2) >> 5,     sc0 = (tid * 2) & 31;
    int srow1 = (tid * 2 + 1) >> 5, sc1 = (tid * 2 + 1) & 31;

    // prologue: load chunk 0
    float4 r0 = *(const float4*)&W2[(size_t)srow0 * DIM + sc0 * 4];
    float4 r1 = *(const float4*)&W2[(size_t)srow1 * DIM + sc1 * 4];
    *(float4*)&w2c[srow0 * 128 + sc0 * 4] = r0;
    *(float4*)&w2c[srow1 * 128 + sc1 * 4] = r1;
    __syncthreads();

    float acc = b2[c];
    for (int ch = 0; ch < 16; ch++) {
        int kc = ch * 32;
        // issue next chunk's loads (latency overlapped with compute below)
        if (ch + 1 < 16) {
            int kn = kc + 32;
            r0 = *(const float4*)&W2[(size_t)(kn + srow0) * DIM + sc0 * 4];
            r1 = *(const float4*)&W2[(size_t)(kn + srow1) * DIM + sc1 * 4];
        }
        #pragma unroll 8
        for (int kk = 0; kk < 32; kk++)
            acc = fmaf(hbufs[g][kc + kk], w2c[kk * 128 + c], acc);
        __syncthreads();
        if (ch + 1 < 16) {
            *(float4*)&w2c[srow0 * 128 + sc0 * 4] = r0;
            *(float4*)&w2c[srow1 * 128 + sc1 * 4] = r1;
        }
        __syncthreads();
    }
    ysm[g][c] = acc;
    __syncthreads();

    // residual + layernorm: warps 0..3, one graph each
    {
        int w = tid >> 5, lane = tid & 31;
        if (w < 4) {
            int gg = gbase + w;
            float4 v  = *(const float4*)&ysm[w][lane * 4];
            float4 uu = *(const float4*)&u[(size_t)gg * DIM + lane * 4];
            v.x += uu.x; v.y += uu.y; v.z += uu.z; v.w += uu.w;

            float sm = v.x + v.y + v.z + v.w;
            #pragma unroll
            for (int off = 16; off; off >>= 1) sm += __shfl_xor_sync(0xffffffffu, sm, off);
            float mu = sm * (1.0f / DIM);

            float dx = v.x - mu, dy = v.y - mu, dz = v.z - mu, dw = v.w - mu;
            float sq = dx * dx + dy * dy + dz * dz + dw * dw;
            #pragma unroll
            for (int off = 16; off; off >>= 1) sq += __shfl_xor_sync(0xffffffffu, sq, off);
            float rs = rsqrtf(sq * (1.0f / DIM) + 1e-5f);

            float4 gm = *(const float4*)&gamma[lane * 4];
            float4 bt = *(const float4*)&beta[lane * 4];
            float4 o;
            o.x = dx * rs * gm.x + bt.x;
            o.y = dy * rs * gm.y + bt.y;
            o.z = dz * rs * gm.z + bt.z;
            o.w = dw * rs * gm.w + bt.w;
            *(float4*)&out[(size_t)gg * DIM + lane * 4] = o;
        }
    }
}

// ---------------------------------------------------------------------------
extern "C" void kernel_launch(void* const* d_in, const int* in_sizes, int n_in,
                              void* d_out, int out_size) {
    const float* x         = (const float*)d_in[0];
    const float* edge_attr = (const float*)d_in[1];
    const float* u         = (const float*)d_in[2];
    const float* W1        = (const float*)d_in[3];
    const float* b1        = (const float*)d_in[4];
    const float* W2        = (const float*)d_in[5];
    const float* b2        = (const float*)d_in[6];
    const float* gamma     = (const float*)d_in[7];
    const float* beta      = (const float*)d_in[8];
    const void* edge_index = d_in[9];
    const void* batch      = d_in[10];

    int n_edges = in_sizes[9] / 2;
    int n_nodes = in_sizes[10];
    float* out = (float*)d_out;

    edgenode_kernel<<<EB + NG, 256>>>(edge_attr, x, edge_index, batch,
                                      n_edges, n_nodes);                   // 1
    reduce_kernel<<<NG, 128>>>();                                          // 2
    mlp1_kernel<<<256, 256>>>(u, W1, b1);                                  // 3
    mlp2_kernel<<<256, 512>>>(u, W2, b2, gamma, beta, out);                // 4 <- ncu slot
}

// round 17
// speedup vs baseline: 1.2385x; 1.0025x over previous
#include <cuda_runtime.h>
#include <cstdint>

#define NG    1024
#define DIM   128
#define HID   512
#define NREP  16
#define EB    1184     // edge blocks in fused kernel

// ---- scratch (no allocations allowed) ----
// Zero-initialized at load; reduce_kernel re-zeroes in-place after consuming,
// so every kernel_launch call observes zeroed scratch (graph-replay safe).
__device__ float    d_escratch[NREP * NG * DIM];   // 8 MB replicated edge sums
__device__ unsigned d_ecnt[NREP * NG];             // replicated edge counts
__device__ float    d_edge_mean[NG * DIM];
__device__ float    d_node_mean[NG * DIM];
__device__ float    d_hbuf[NG * HID];              // hidden activations (2 MB)

// ---------------------------------------------------------------------------
__device__ __forceinline__ int load_idx(const void* p, long long i, int idx64) {
    return idx64 ? (int)((const long long*)p)[i] : ((const int*)p)[i];
}
// dtype probe on edge_index: node ids are random nonzero ints, so
// all-zero odd 32-bit words <=> int64 storage.
__device__ __forceinline__ int probe_idx64(const void* edge_index) {
    const int* w = (const int*)edge_index;
    int all_zero = 1;
    #pragma unroll
    for (int i = 1; i < 128; i += 2) all_zero &= (w[i] == 0);
    return all_zero;
}

// red.global.add.v4 WITHOUT a memory clobber: fire-and-forget atomic; register
// deps keep it correct and the compiler can overlap subsequent loads.
__device__ __forceinline__ void red_add_v4(float* dst, float4 v) {
    asm volatile("red.global.add.v4.f32 [%0], {%1,%2,%3,%4};"
                 :: "l"(dst), "f"(v.x), "f"(v.y), "f"(v.z), "f"(v.w));
}

// ---------------------------------------------------------------------------
// K1: blocks 0..EB-1 -> edge scatter (4 edges/iter, parallel index chains)
//     blocks EB..    -> node mean (block per graph, self-computed bounds)
// Plain (default-policy) loads everywhere: graph replays re-read edge_attr/x,
// and L2 retention across replays matters more than cold-run behavior.
// ---------------------------------------------------------------------------
__global__ void __launch_bounds__(256) edgenode_kernel(
        const float* __restrict__ edge_attr,
        const float* __restrict__ x,
        const void* __restrict__ edge_index,
        const void* __restrict__ batch,
        int n_edges, int n_nodes) {
    int b = blockIdx.x, tid = threadIdx.x;
    int lane = tid & 31;

    if (b < EB) {
        __shared__ int s_idx64;
        if (tid == 0) s_idx64 = probe_idx64(edge_index);
        __syncthreads();
        int idx64 = s_idx64;

        int warp_g = (b * 256 + tid) >> 5;
        int nwarps = (EB * 256) >> 5;
        int stride = nwarps * 4;
        int rep    = warp_g & (NREP - 1);
        const float4* ea = (const float4*)edge_attr;

        // lanes 0..3 each own one index chain per 4-edge batch
        int e = warp_g * 4;
        int gcur = 0;
        if (lane < 4 && e + lane < n_edges) {
            int src = load_idx(edge_index, e + lane, idx64);
            gcur = load_idx(batch, src, idx64);
        }

        for (; e < n_edges; e += stride) {
            // prefetch next batch's graph ids (independent chains)
            int en = e + stride;
            int gnxt = 0;
            if (lane < 4 && en + lane < n_edges) {
                int src = load_idx(edge_index, en + lane, idx64);
                gnxt = load_idx(batch, src, idx64);
            }

            int g0 = __shfl_sync(0xffffffffu, gcur, 0);
            int g1 = __shfl_sync(0xffffffffu, gcur, 1);
            int g2 = __shfl_sync(0xffffffffu, gcur, 2);
            int g3 = __shfl_sync(0xffffffffu, gcur, 3);

            // 4 independent row loads
            float4 v0, v1, v2, v3;
            int h1 = (e + 1 < n_edges), h2 = (e + 2 < n_edges), h3 = (e + 3 < n_edges);
            v0 = ea[(size_t)e * 32 + lane];
            v1 = h1 ? ea[(size_t)(e + 1) * 32 + lane] : make_float4(0, 0, 0, 0);
            v2 = h2 ? ea[(size_t)(e + 2) * 32 + lane] : make_float4(0, 0, 0, 0);
            v3 = h3 ? ea[(size_t)(e + 3) * 32 + lane] : make_float4(0, 0, 0, 0);

            red_add_v4(d_escratch + ((size_t)rep * NG + g0) * DIM + lane * 4, v0);
            if (h1) red_add_v4(d_escratch + ((size_t)rep * NG + g1) * DIM + lane * 4, v1);
            if (h2) red_add_v4(d_escratch + ((size_t)rep * NG + g2) * DIM + lane * 4, v2);
            if (h3) red_add_v4(d_escratch + ((size_t)rep * NG + g3) * DIM + lane * 4, v3);

            // lane-parallel edge counts (lane i holds g_i)
            if (lane < 4 && e + lane < n_edges)
                atomicAdd(&d_ecnt[rep * NG + gcur], 1u);

            gcur = gnxt;
        }
    } else {
        // node mean: graph g's rows are contiguous in x (batch is sorted)
        int g = b - EB;
        __shared__ int s_bound[2];
        if (tid < 2) {
            int idx64 = probe_idx64(edge_index);
            int target = g + tid;
            int lo = 0, hi = n_nodes;
            while (lo < hi) {
                int m = (lo + hi) >> 1;
                if (load_idx(batch, m, idx64) < target) lo = m + 1; else hi = m;
            }
            s_bound[tid] = lo;
        }
        __syncthreads();
        int s = s_bound[0], e = s_bound[1];
        int cnt = e - s;
        int w = tid >> 5;

        const float4* xr = (const float4*)x;
        float4 acc = make_float4(0.f, 0.f, 0.f, 0.f);
        for (int n = s + w; n < e; n += 8) {
            float4 v = xr[(size_t)n * 32 + lane];
            acc.x += v.x; acc.y += v.y; acc.z += v.z; acc.w += v.w;
        }
        __shared__ float4 s_red[8][32];
        s_red[w][lane] = acc;
        __syncthreads();
        if (w == 0) {
            float4 t = s_red[0][lane];
            #pragma unroll
            for (int i = 1; i < 8; i++) {
                float4 q = s_red[i][lane];
                t.x += q.x; t.y += q.y; t.z += q.z; t.w += q.w;
            }
            float inv = 1.0f / (float)(cnt > 0 ? cnt : 1);
            t.x *= inv; t.y *= inv; t.z *= inv; t.w *= inv;
            ((float4*)(d_node_mean + (size_t)g * DIM))[lane] = t;
        }
    }
}

// ---------------------------------------------------------------------------
// K2 (reduce): 1024 blocks (one graph each) x 128 threads.
// Coalesced replica reduce + in-place zero; trivially parallel.
// ---------------------------------------------------------------------------
__global__ void __launch_bounds__(128) reduce_kernel() {
    __shared__ unsigned sc[NREP];
    __shared__ float s_inv;
    int g = blockIdx.x, t = threadIdx.x;

    if (t < NREP) {
        sc[t] = d_ecnt[t * NG + g];
        d_ecnt[t * NG + g] = 0u;
    }
    __syncthreads();
    if (t == 0) {
        unsigned c = 0;
        #pragma unroll
        for (int r = 0; r < NREP; r++) c += sc[r];
        s_inv = 1.0f / (float)(c > 0u ? c : 1u);
    }
    __syncthreads();

    float s = 0.f;
    #pragma unroll
    for (int r = 0; r < NREP; r++) {
        size_t off = ((size_t)r * NG + g) * DIM + t;
        s += d_escratch[off];
        d_escratch[off] = 0.f;
    }
    d_edge_mean[(size_t)g * DIM + t] = s * s_inv;
}

// ---------------------------------------------------------------------------
// K3 (mlp1): h = relu(inp @ W1 + b1), W1 staged in smem.
// 256 blocks = 16 col-slices (32 cols) x 16 graph-tiles (64 graphs).
// ---------------------------------------------------------------------------
__global__ void __launch_bounds__(256) mlp1_kernel(
        const float* __restrict__ u,
        const float* __restrict__ W1, const float* __restrict__ b1) {
    __shared__ float w1c[64 * 32];        // 8 KB: W1 chunk [64 k][32 cols]
    __shared__ float inps[64 * 65];       // 16.6 KB: inp [64 g][64 k + pad]

    int bI = blockIdx.x;
    int sl = bI & 15;          // col slice (32 cols)
    int tI = bI >> 4;          // graph tile (64 graphs)
    int gbase = tI * 64;
    int tid = threadIdx.x;
    int tx = tid & 7, ty = tid >> 3;

    float4 bb = *(const float4*)&b1[sl * 32 + tx * 4];
    float acc[2][4];
    #pragma unroll
    for (int gi = 0; gi < 2; gi++) {
        acc[gi][0] = bb.x; acc[gi][1] = bb.y; acc[gi][2] = bb.z; acc[gi][3] = bb.w;
    }

    for (int ch = 0; ch < 6; ch++) {
        int kc = ch * 64;
        __syncthreads();   // protect smem from previous chunk's readers

        // stage W1 chunk [64 rows][32 cols]: 512 float4, 2 per thread
        #pragma unroll
        for (int p = 0; p < 2; p++) {
            int idx = tid + p * 256;
            int row = idx >> 3, cc = idx & 7;
            *(float4*)&w1c[row * 32 + cc * 4] =
                *(const float4*)&W1[(size_t)(kc + row) * HID + sl * 32 + cc * 4];
        }
        // stage inp chunk [64 graphs][64 features]: 1024 float4
        #pragma unroll
        for (int p = 0; p < 4; p++) {
            int idx = tid + p * 256;
            int g = idx >> 4, kq = idx & 15;
            int gg = gbase + g;
            float4 v;
            if (ch < 2) {
                v = *(const float4*)&u[(size_t)gg * DIM + kc + kq * 4];
            } else if (ch < 4) {
                v = *(const float4*)&d_edge_mean[(size_t)gg * DIM + kc - 128 + kq * 4];
            } else {
                v = *(const float4*)&d_node_mean[(size_t)gg * DIM + kc - 256 + kq * 4];
            }
            float* dst = &inps[g * 65 + kq * 4];
            dst[0] = v.x; dst[1] = v.y; dst[2] = v.z; dst[3] = v.w;
        }
        __syncthreads();

        #pragma unroll 4
        for (int kk = 0; kk < 64; kk++) {
            float4 wv = *(const float4*)&w1c[kk * 32 + tx * 4];
            float x0 = inps[(ty * 2 + 0) * 65 + kk];
            float x1 = inps[(ty * 2 + 1) * 65 + kk];
            acc[0][0] = fmaf(x0, wv.x, acc[0][0]); acc[0][1] = fmaf(x0, wv.y, acc[0][1]);
            acc[0][2] = fmaf(x0, wv.z, acc[0][2]); acc[0][3] = fmaf(x0, wv.w, acc[0][3]);
            acc[1][0] = fmaf(x1, wv.x, acc[1][0]); acc[1][1] = fmaf(x1, wv.y, acc[1][1]);
            acc[1][2] = fmaf(x1, wv.z, acc[1][2]); acc[1][3] = fmaf(x1, wv.w, acc[1][3]);
        }
    }

    // write h with relu (float4)
    #pragma unroll
    for (int gi = 0; gi < 2; gi++) {
        int gg = gbase + ty * 2 + gi;
        float4 o;
        o.x = fmaxf(acc[gi][0], 0.f); o.y = fmaxf(acc[gi][1], 0.f);
        o.z = fmaxf(acc[gi][2], 0.f); o.w = fmaxf(acc[gi][3], 0.f);
        *(float4*)&d_hbuf[(size_t)gg * HID + sl * 32 + tx * 4] = o;
    }
}

// ---------------------------------------------------------------------------
// K4 (mlp2): y = LayerNorm(h @ W2 + b2 + u).
// 256 blocks x 4 graphs, 512 threads. h staged once; W2 in 32-row chunks with
// register double-buffering (load next chunk while computing current).
// ---------------------------------------------------------------------------
__global__ void __launch_bounds__(512) mlp2_kernel(
        const float* __restrict__ u,
        const float* __restrict__ W2, const float* __restrict__ b2,
        const float* __restrict__ gamma, const float* __restrict__ beta,
        float* __restrict__ out) {
    __shared__ float hbufs[4][HID];    // 8 KB: full h rows for 4 graphs
    __shared__ float w2c[32 * 128];    // 16 KB: W2 chunk [32 k][128 cols]
    __shared__ float ysm[4][DIM];      // 2 KB

    int bI = blockIdx.x;
    int gbase = bI * 4;
    int tid = threadIdx.x;
    int g = tid >> 7;           // 0..3
    int c = tid & 127;          // output col

    // stage h fully: 4 x 512 floats = 512 float4, one per thread
    {
        int gi = tid >> 7, k4 = tid & 127;
        *(float4*)&hbufs[gi][k4 * 4] =
            *(const float4*)&d_hbuf[(size_t)(gbase + gi) * HID + k4 * 4];
    }

    // chunk staging: 32 rows x 128 cols = 1024 float4; 512 threads -> 2 each
    int srow0 = (tid * 2) >> 5,     sc0 = (tid * 2) & 31;
    int srow1 = (tid * 2 + 1) >> 5, sc1 = (tid * 2 + 1) & 31;

    // prologue: load chunk 0
    float4 r0 = *(const float4*)&W2[(size_t)srow0 * DIM + sc0 * 4];
    float4 r1 = *(const float4*)&W2[(size_t)srow1 * DIM + sc1 * 4];
    *(float4*)&w2c[srow0 * 128 + sc0 * 4] = r0;
    *(float4*)&w2c[srow1 * 128 + sc1 * 4] = r1;
    __syncthreads();

    float acc = b2[c];
    for (int ch = 0; ch < 16; ch++) {
        int kc = ch * 32;
        // issue next chunk's loads (latency overlapped with compute below)
        if (ch + 1 < 16) {
            int kn = kc + 32;
            r0 = *(const float4*)&W2[(size_t)(kn + srow0) * DIM + sc0 * 4];
            r1 = *(const float4*)&W2[(size_t)(kn + srow1) * DIM + sc1 * 4];
        }
        #pragma unroll 8
        for (int kk = 0; kk < 32; kk++)
            acc = fmaf(hbufs[g][kc + kk], w2c[kk * 128 + c], acc);
        __syncthreads();
        if (ch + 1 < 16) {
            *(float4*)&w2c[srow0 * 128 + sc0 * 4] = r0;
            *(float4*)&w2c[srow1 * 128 + sc1 * 4] = r1;
        }
        __syncthreads();
    }
    ysm[g][c] = acc;
    __syncthreads();

    // residual + layernorm: warps 0..3, one graph each
    {
        int w = tid >> 5, lane = tid & 31;
        if (w < 4) {
            int gg = gbase + w;
            float4 v  = *(const float4*)&ysm[w][lane * 4];
            float4 uu = *(const float4*)&u[(size_t)gg * DIM + lane * 4];
            v.x += uu.x; v.y += uu.y; v.z += uu.z; v.w += uu.w;

            float sm = v.x + v.y + v.z + v.w;
            #pragma unroll
            for (int off = 16; off; off >>= 1) sm += __shfl_xor_sync(0xffffffffu, sm, off);
            float mu = sm * (1.0f / DIM);

            float dx = v.x - mu, dy = v.y - mu, dz = v.z - mu, dw = v.w - mu;
            float sq = dx * dx + dy * dy + dz * dz + dw * dw;
            #pragma unroll
            for (int off = 16; off; off >>= 1) sq += __shfl_xor_sync(0xffffffffu, sq, off);
            float rs = rsqrtf(sq * (1.0f / DIM) + 1e-5f);

            float4 gm = *(const float4*)&gamma[lane * 4];
            float4 bt = *(const float4*)&beta[lane * 4];
            float4 o;
            o.x = dx * rs * gm.x + bt.x;
            o.y = dy * rs * gm.y + bt.y;
            o.z = dz * rs * gm.z + bt.z;
            o.w = dw * rs * gm.w + bt.w;
            *(float4*)&out[(size_t)gg * DIM + lane * 4] = o;
        }
    }
}

// ---------------------------------------------------------------------------
extern "C" void kernel_launch(void* const* d_in, const int* in_sizes, int n_in,
                              void* d_out, int out_size) {
    const float* x         = (const float*)d_in[0];
    const float* edge_attr = (const float*)d_in[1];
    const float* u         = (const float*)d_in[2];
    const float* W1        = (const float*)d_in[3];
    const float* b1        = (const float*)d_in[4];
    const float* W2        = (const float*)d_in[5];
    const float* b2        = (const float*)d_in[6];
    const float* gamma     = (const float*)d_in[7];
    const float* beta      = (const float*)d_in[8];
    const void* edge_index = d_in[9];
    const void* batch      = d_in[10];

    int n_edges = in_sizes[9] / 2;
    int n_nodes = in_sizes[10];
    float* out = (float*)d_out;

    edgenode_kernel<<<EB + NG, 256>>>(edge_attr, x, edge_index, batch,
                                      n_edges, n_nodes);                   // 1
    reduce_kernel<<<NG, 128>>>();                                          // 2
    mlp1_kernel<<<256, 256>>>(u, W1, b1);                                  // 3
    mlp2_kernel<<<256, 512>>>(u, W2, b2, gamma, beta, out);                // 4 <- ncu slot
}